// round 14
// baseline (speedup 1.0000x reference)
#include <cuda_runtime.h>
#include <cuda_fp16.h>
#include <cstdint>

#define BB 2
#define CC 128
#define NN 4096
#define LOG2E 1.4426950408889634f

// Device scratch
__device__ __align__(16) __half g_wh[3 * CC * CC]; // W fp16 hi (x64), [m][c_out][k]
__device__ __align__(16) __half g_wl[3 * CC * CC]; // W fp16 lo (x64)
__device__ __half g_qh[BB * NN * CC];      // [b][n][c]  fp16, pre-scaled by log2e
__device__ __half g_kh[BB * NN * CC];      // [b][n][c]  fp16
__device__ __half g_vh[BB * CC * NN];      // [b][c][n]  fp16
__device__ float g_part[2 * BB * CC * NN]; // [half][b][c][n] partial O
__device__ float g_lsum[2 * BB * NN];      // [half][b][n] partial row sums

// ============================ helpers ============================
__device__ __forceinline__ uint32_t smem_u32(const void* p) {
    uint32_t a;
    asm("{ .reg .u64 t; cvta.to.shared.u64 t, %1; cvt.u32.u64 %0, t; }"
        : "=r"(a) : "l"(p));
    return a;
}
__device__ __forceinline__ uint32_t ex2_h2(uint32_t x) {
    uint32_t r;
    asm("ex2.approx.f16x2 %0, %1;" : "=r"(r) : "r"(x));
    return r;
}
__device__ __forceinline__ uint32_t pack_h2(float lo, float hi) {
    __half2 h = __floats2half2_rn(lo, hi);
    return *reinterpret_cast<uint32_t*>(&h);
}

#define MMA_F16(d, a, b0, b1) \
    asm volatile("mma.sync.aligned.m16n8k16.row.col.f32.f16.f16.f32 " \
        "{%0,%1,%2,%3}, {%4,%5,%6,%7}, {%8,%9}, {%0,%1,%2,%3};" \
        : "+f"((d)[0]), "+f"((d)[1]), "+f"((d)[2]), "+f"((d)[3]) \
        : "r"((a)[0]), "r"((a)[1]), "r"((a)[2]), "r"((a)[3]), "r"(b0), "r"(b1))

#define LDSM_X4(r0, r1, r2, r3, addr) \
    asm volatile("ldmatrix.sync.aligned.m8n8.x4.shared.b16 {%0,%1,%2,%3}, [%4];" \
        : "=r"(r0), "=r"(r1), "=r"(r2), "=r"(r3) : "r"(addr))

#define CPA(dst, src) \
    asm volatile("cp.async.cg.shared.global [%0], [%1], 16;" :: "r"(dst), "l"(src))
#define CPA_COMMIT asm volatile("cp.async.commit_group;" ::: "memory")
#define CPA_WAIT0  asm volatile("cp.async.wait_group 0;" ::: "memory")
#define NAMED_BAR(id, cnt) \
    asm volatile("bar.sync %0, %1;" :: "r"(id), "r"(cnt) : "memory")

#define INV64 0.015625f

// ============================ W prep: fp32 -> fp16 hi/lo (x64) ============================
__global__ __launch_bounds__(256)
void wprep(const float* __restrict__ Wq, const float* __restrict__ Wk,
           const float* __restrict__ Wv) {
    int m = blockIdx.y;
    const float* W = (m == 0) ? Wq : (m == 1) ? Wk : Wv;
    int i = blockIdx.x * 256 + threadIdx.x;
    float f = W[i] * 64.0f;
    __half h = __float2half_rn(f);
    g_wh[m * CC * CC + i] = h;
    g_wl[m * CC * CC + i] = __float2half_rn(f - __half2float(h));
}

// ============================ QKV v7: 512 threads, concurrent Q|K GEMMs ============================
// SMEM halves: W0hi[128][136] | W0lo | W1hi | W1lo | XhiT[64][136] | XloT | Xf32/stage
#define WB0HI 0
#define WB0LO 17408
#define WB1HI 34816
#define WB1LO 52224
#define XHI   69632
#define XLO   78336
#define XFH   87040
#define SMEM_QKV6 ((87040 + 18432) * 2)

template<int NTN>
__device__ __forceinline__ void qkv_gemm(uint32_t sbase, const __half* smh,
                                         int whi, int wlo, int crow_base, int nt0,
                                         int lane, float (*acc)[4]) {
    const uint32_t* Xhi32 = (const uint32_t*)(smh + XHI);
    const uint32_t* Xlo32 = (const uint32_t*)(smh + XLO);
    int g = lane >> 2, t = lane & 3;
    uint32_t aoff = (uint32_t)((crow_base + (lane & 15)) * 136 + ((lane >> 4) << 3));
    #pragma unroll
    for (int ko = 0; ko < 8; ko++) {
        uint32_t ahi[4], alo[4];
        LDSM_X4(ahi[0], ahi[1], ahi[2], ahi[3], sbase + (uint32_t)(whi + aoff + ko * 16) * 2);
        LDSM_X4(alo[0], alo[1], alo[2], alo[3], sbase + (uint32_t)(wlo + aoff + ko * 16) * 2);
        #pragma unroll
        for (int j = 0; j < NTN; j++) {
            int nt = nt0 + j;
            int i0 = (nt * 8 + g) * 68 + ko * 8 + t;
            uint32_t bh0 = Xhi32[i0], bh1 = Xhi32[i0 + 4];
            uint32_t bl0 = Xlo32[i0], bl1 = Xlo32[i0 + 4];
            MMA_F16(acc[j], alo, bh0, bh1);
            MMA_F16(acc[j], ahi, bl0, bl1);
            MMA_F16(acc[j], ahi, bh0, bh1);
        }
    }
}

__global__ __launch_bounds__(512, 1)
void qkv6(const float* __restrict__ x,
          const float* __restrict__ bq, const float* __restrict__ bk,
          const float* __restrict__ bv) {
    extern __shared__ __half smh[];
    uint32_t sbase = smem_u32(smh);

    int n0 = blockIdx.x * 64;
    int b = blockIdx.y;
    const float* xb = x + (size_t)b * CC * NN;

    int tid = threadIdx.x;
    int w = tid >> 5, lane = tid & 31;
    int g = lane >> 2, t = lane & 3;
    int tile = w & 7, grp = w >> 3;
    int crow = tile * 16 + g;

    // ---- prologue: W0 hi/lo, W1 hi/lo (fp16), X (fp32) ----
    #pragma unroll
    for (int it = 0; it < 4; it++) {
        int i = tid + it * 512;                 // 0..2047
        int r = i >> 4, c8 = (i & 15) << 3;
        CPA(sbase + (uint32_t)(WB0HI + r * 136 + c8) * 2, g_wh + r * CC + c8);
        CPA(sbase + (uint32_t)(WB0LO + r * 136 + c8) * 2, g_wl + r * CC + c8);
        CPA(sbase + (uint32_t)(WB1HI + r * 136 + c8) * 2, g_wh + CC * CC + r * CC + c8);
        CPA(sbase + (uint32_t)(WB1LO + r * 136 + c8) * 2, g_wl + CC * CC + r * CC + c8);
    }
    #pragma unroll
    for (int it = 0; it < 4; it++) {
        int i = tid + it * 512;
        int r = i >> 4, n4 = (i & 15) << 2;
        CPA(sbase + (uint32_t)XFH * 2 + (uint32_t)(r * 72 + n4) * 4, xb + (size_t)r * NN + n0 + n4);
    }
    CPA_COMMIT;
    CPA_WAIT0;
    __syncthreads();

    // ---- convert X -> transposed fp16 hi/lo tiles [n][k] (512 threads) ----
    {
        const float* Xf = (const float*)(smh + XFH);
        int n = tid >> 3;
        int kb = (tid & 7) * 16;
        uint32_t* XhiT = (uint32_t*)(smh + XHI);
        uint32_t* XloT = (uint32_t*)(smh + XLO);
        #pragma unroll
        for (int j = 0; j < 8; j++) {
            int k = kb + 2 * j;
            float f0 = Xf[k * 72 + n];
            float f1 = Xf[(k + 1) * 72 + n];
            __half h0 = __float2half_rn(f0), h1 = __float2half_rn(f1);
            XhiT[n * 68 + (kb >> 1) + j] = pack_h2(__half2float(h0), __half2float(h1));
            XloT[n * 68 + (kb >> 1) + j] = pack_h2(f0 - __half2float(h0), f1 - __half2float(h1));
        }
    }
    __syncthreads();

    // ---- phase 1: group 0 -> Q (buf0), group 1 -> K (buf1), concurrent ----
    {
        float acc[8][4] = {};
        qkv_gemm<8>(sbase, smh, grp ? WB1HI : WB0HI, grp ? WB1LO : WB0LO,
                    tile * 16, 0, lane, acc);

        const float* bias = grp ? bk : bq;
        float b0v = bias[crow], b1v = bias[crow + 8];
        float qs = grp ? 1.0f : LOG2E;
        __half* st = smh + XFH + grp * 8704;

        #pragma unroll
        for (int nt = 0; nt < 8; nt++) {
            int n = nt * 8 + 2 * t;
            st[n * 136 + crow]           = __float2half_rn((acc[nt][0] * INV64 + b0v) * qs);
            st[(n + 1) * 136 + crow]     = __float2half_rn((acc[nt][1] * INV64 + b0v) * qs);
            st[n * 136 + crow + 8]       = __float2half_rn((acc[nt][2] * INV64 + b1v) * qs);
            st[(n + 1) * 136 + crow + 8] = __float2half_rn((acc[nt][3] * INV64 + b1v) * qs);
        }
        NAMED_BAR(grp + 1, 256);
        __half* out = (grp ? g_kh : g_qh) + ((size_t)b * NN + n0) * CC;
        int gtid = tid & 255;
        #pragma unroll
        for (int it = 0; it < 4; it++) {
            int i = gtid + it * 256;
            int r = i >> 4, c8 = (i & 15) << 3;
            *(uint4*)(out + (size_t)r * CC + c8) = *(uint4*)&st[r * 136 + c8];
        }
    }
    __syncthreads();

    // ---- load W2 into buf0 ----
    #pragma unroll
    for (int it = 0; it < 4; it++) {
        int i = tid + it * 512;
        int r = i >> 4, c8 = (i & 15) << 3;
        CPA(sbase + (uint32_t)(WB0HI + r * 136 + c8) * 2, g_wh + 2 * CC * CC + r * CC + c8);
        CPA(sbase + (uint32_t)(WB0LO + r * 136 + c8) * 2, g_wl + 2 * CC * CC + r * CC + c8);
    }
    CPA_COMMIT;
    CPA_WAIT0;
    __syncthreads();

    // ---- phase 2: V, all 16 warps (n-split by group) ----
    {
        float acc[4][4] = {};
        int nt0 = grp * 4;
        qkv_gemm<4>(sbase, smh, WB0HI, WB0LO, tile * 16, nt0, lane, acc);

        float b0v = bv[crow], b1v = bv[crow + 8];
        __half* st = smh + XFH;
        #pragma unroll
        for (int j = 0; j < 4; j++) {
            int n = (nt0 + j) * 8 + 2 * t;
            *(__half2*)&st[crow * 72 + n] =
                __floats2half2_rn(acc[j][0] * INV64 + b0v, acc[j][1] * INV64 + b0v);
            *(__half2*)&st[(crow + 8) * 72 + n] =
                __floats2half2_rn(acc[j][2] * INV64 + b1v, acc[j][3] * INV64 + b1v);
        }
        __syncthreads();
        __half* out = g_vh + (size_t)b * CC * NN + n0;
        #pragma unroll
        for (int it = 0; it < 2; it++) {
            int i = tid + it * 512;
            int r = i >> 3, n8 = (i & 7) << 3;
            *(uint4*)(out + (size_t)r * NN + n8) = *(uint4*)&st[r * 72 + n8];
        }
    }
}

// ============================ flash v9 (unchanged, proven R13) ============================
#define FS 136
#define OFFK 17408
#define OFFV 52224
#define FB 17408
#define SMEM_FLASH9 (87040 * 2)
#define ONES2 0x3C003C00u

__global__ __launch_bounds__(256, 1)
void flash9() {
    extern __shared__ __half smh[];
    uint32_t sbase = smem_u32(smh);

    int tid = threadIdx.x;
    int w = tid >> 5, lane = tid & 31;
    int g = lane >> 2, t = lane & 3;
    int qrow = w * 16 + g;

    int lrow = (lane & 7) + ((lane >> 4) & 1) * 8;
    int lkof = ((lane >> 3) & 1) * 8;
    uint32_t laneoff = (uint32_t)(lrow * FS + lkof) * 2;

    int qtile = blockIdx.x, half = blockIdx.y, b = blockIdx.z;
    const __half* qg = g_qh + ((size_t)b * NN + (size_t)qtile * 128) * CC;
    const __half* kg = g_kh + ((size_t)b * NN + (size_t)half * 2048) * CC;
    const __half* vg = g_vh + (size_t)b * CC * NN + (size_t)half * 2048;

    #pragma unroll
    for (int it = 0; it < 8; it++) {
        int i = tid + it * 256;
        int r = i >> 4, c16 = i & 15;
        CPA(sbase + (uint32_t)(r * FS * 2 + c16 * 16), qg + (size_t)r * CC + c16 * 8);
    }
    #pragma unroll
    for (int it = 0; it < 8; it++) {
        int i = tid + it * 256;
        int r = i >> 4, c16 = i & 15;
        CPA(sbase + (uint32_t)(OFFK * 2 + r * FS * 2 + c16 * 16), kg + (size_t)r * CC + c16 * 8);
    }
    #pragma unroll
    for (int it = 0; it < 8; it++) {
        int i = tid + it * 256;
        int c = i >> 4, k16 = i & 15;
        CPA(sbase + (uint32_t)(OFFV * 2 + c * FS * 2 + k16 * 16), vg + (size_t)c * NN + k16 * 8);
    }
    CPA_COMMIT;
    CPA_WAIT0;
    __syncthreads();

    uint32_t qa[8][4];
    #pragma unroll
    for (int ko = 0; ko < 8; ko++) {
        const __half* qp = smh + qrow * FS + ko * 16;
        qa[ko][0] = *(const uint32_t*)(qp + 2 * t);
        qa[ko][1] = *(const uint32_t*)(qp + 8 * FS + 2 * t);
        qa[ko][2] = *(const uint32_t*)(qp + 2 * t + 8);
        qa[ko][3] = *(const uint32_t*)(qp + 8 * FS + 2 * t + 8);
    }
    __syncthreads();

    float o[16][4] = {};
    float rsacc[4] = {};

    for (int kb = 0; kb < 16; kb++) {
        int buf = kb & 1;
        if (kb < 15) {
            int m0 = (kb + 1) * 128;
            int nb = buf ^ 1;
            #pragma unroll
            for (int it = 0; it < 8; it++) {
                int i = tid + it * 256;
                int r = i >> 4, c16 = i & 15;
                CPA(sbase + (uint32_t)((OFFK + nb * FB) * 2 + r * FS * 2 + c16 * 16),
                    kg + (size_t)(m0 + r) * CC + c16 * 8);
            }
            #pragma unroll
            for (int it = 0; it < 8; it++) {
                int i = tid + it * 256;
                int c = i >> 4, k16 = i & 15;
                CPA(sbase + (uint32_t)((OFFV + nb * FB) * 2 + c * FS * 2 + k16 * 16),
                    vg + (size_t)c * NN + m0 + k16 * 8);
            }
            CPA_COMMIT;
        }

        uint32_t kaddr = sbase + (uint32_t)(OFFK + buf * FB) * 2 + laneoff;
        uint32_t vaddr = sbase + (uint32_t)(OFFV + buf * FB) * 2 + laneoff;

        uint32_t pa[8][4];
        #pragma unroll
        for (int nh = 0; nh < 2; nh++) {
            float sacc[8][4] = {};
            #pragma unroll
            for (int ko = 0; ko < 8; ko++) {
                #pragma unroll
                for (int np = 0; np < 4; np++) {
                    uint32_t a = kaddr + (uint32_t)(((nh * 4 + np) * 16) * FS + ko * 16) * 2;
                    uint32_t r0, r1, r2, r3;
                    LDSM_X4(r0, r1, r2, r3, a);
                    MMA_F16(sacc[np * 2 + 0], qa[ko], r0, r1);
                    MMA_F16(sacc[np * 2 + 1], qa[ko], r2, r3);
                }
            }
            #pragma unroll
            for (int nt = 0; nt < 8; nt++) {
                pa[nh * 4 + (nt >> 1)][(nt & 1) * 2 + 0] =
                    ex2_h2(pack_h2(sacc[nt][0], sacc[nt][1]));
                pa[nh * 4 + (nt >> 1)][(nt & 1) * 2 + 1] =
                    ex2_h2(pack_h2(sacc[nt][2], sacc[nt][3]));
            }
        }

        #pragma unroll
        for (int kf = 0; kf < 8; kf++)
            MMA_F16(rsacc, pa[kf], ONES2, ONES2);

        #pragma unroll
        for (int kf = 0; kf < 8; kf++) {
            #pragma unroll
            for (int cp = 0; cp < 8; cp++) {
                uint32_t a = vaddr + (uint32_t)((cp * 16) * FS + kf * 16) * 2;
                uint32_t r0, r1, r2, r3;
                LDSM_X4(r0, r1, r2, r3, a);
                MMA_F16(o[cp * 2 + 0], pa[kf], r0, r1);
                MMA_F16(o[cp * 2 + 1], pa[kf], r2, r3);
            }
        }

        CPA_WAIT0;
        __syncthreads();
    }

    if (t == 0) {
        float* gl = g_lsum + (size_t)half * BB * NN + (size_t)b * NN + qtile * 128;
        gl[qrow] = rsacc[0];
        gl[qrow + 8] = rsacc[2];
    }

    float* smf = (float*)smh;
    #pragma unroll
    for (int cn = 0; cn < 16; cn++) {
        int c0 = cn * 8 + 2 * t;
        smf[c0 * 132 + qrow]           = o[cn][0];
        smf[(c0 + 1) * 132 + qrow]     = o[cn][1];
        smf[c0 * 132 + qrow + 8]       = o[cn][2];
        smf[(c0 + 1) * 132 + qrow + 8] = o[cn][3];
    }
    __syncthreads();
    float* gp = g_part + (size_t)half * BB * CC * NN + (size_t)b * CC * NN + (size_t)qtile * 128;
    #pragma unroll
    for (int it = 0; it < 16; it++) {
        int i = tid + it * 256;
        int c = i >> 5, q4 = (i & 31) << 2;
        *(float4*)(gp + (size_t)c * NN + q4) = *(float4*)&smf[c * 132 + q4];
    }
}

// ============================ combine halves ============================
__global__ __launch_bounds__(256)
void combine_kernel(float* __restrict__ out) {
    int idx = blockIdx.x * 256 + threadIdx.x;
    size_t e = (size_t)idx * 4;
    int n = (int)(e & (NN - 1));
    int b = (int)(e / ((size_t)CC * NN));
    float4 p0 = *(const float4*)(g_part + e);
    float4 p1 = *(const float4*)(g_part + (size_t)BB * CC * NN + e);
    float4 l0 = *(const float4*)(g_lsum + (size_t)b * NN + n);
    float4 l1 = *(const float4*)(g_lsum + (size_t)BB * NN + (size_t)b * NN + n);
    float4 o;
    o.x = (p0.x + p1.x) / (l0.x + l1.x);
    o.y = (p0.y + p1.y) / (l0.y + l1.y);
    o.z = (p0.z + p1.z) / (l0.z + l1.z);
    o.w = (p0.w + p1.w) / (l0.w + l1.w);
    *(float4*)(out + e) = o;
}

// ============================ launch ============================
extern "C" void kernel_launch(void* const* d_in, const int* in_sizes, int n_in,
                              void* d_out, int out_size) {
    const float* x  = (const float*)d_in[0];
    const float* Wq = (const float*)d_in[1];
    const float* bq = (const float*)d_in[2];
    const float* Wk = (const float*)d_in[3];
    const float* bk = (const float*)d_in[4];
    const float* Wv = (const float*)d_in[5];
    const float* bv = (const float*)d_in[6];
    float* out = (float*)d_out;

    dim3 gw(CC * CC / 256, 3);
    wprep<<<gw, 256>>>(Wq, Wk, Wv);

    cudaFuncSetAttribute(qkv6, cudaFuncAttributeMaxDynamicSharedMemorySize, SMEM_QKV6);
    dim3 gq(NN / 64, BB);
    qkv6<<<gq, 512, SMEM_QKV6>>>(x, bq, bk, bv);

    cudaFuncSetAttribute(flash9, cudaFuncAttributeMaxDynamicSharedMemorySize, SMEM_FLASH9);
    dim3 gf(NN / 128, 2, BB);
    flash9<<<gf, 256, SMEM_FLASH9>>>();

    combine_kernel<<<(BB * CC * NN / 4) / 256, 256>>>(out);
}

// round 15
// speedup vs baseline: 1.0219x; 1.0219x over previous
#include <cuda_runtime.h>
#include <cuda_fp16.h>
#include <cstdint>

#define BB 2
#define CC 128
#define NN 4096
#define LOG2E 1.4426950408889634f

// Device scratch
__device__ __half g_qh[BB * NN * CC];      // [b][n][c]  fp16, pre-scaled by log2e
__device__ __half g_kh[BB * NN * CC];      // [b][n][c]  fp16
__device__ __half g_vh[BB * CC * NN];      // [b][c][n]  fp16
__device__ __half g_ph[2 * BB * CC * NN];  // [half][b][c][n] partial O (fp16)
__device__ float g_lsum[2 * BB * NN];      // [half][b][n] partial row sums

// ============================ helpers ============================
__device__ __forceinline__ uint32_t smem_u32(const void* p) {
    uint32_t a;
    asm("{ .reg .u64 t; cvta.to.shared.u64 t, %1; cvt.u32.u64 %0, t; }"
        : "=r"(a) : "l"(p));
    return a;
}
__device__ __forceinline__ uint32_t ex2_h2(uint32_t x) {
    uint32_t r;
    asm("ex2.approx.f16x2 %0, %1;" : "=r"(r) : "r"(x));
    return r;
}
__device__ __forceinline__ uint32_t pack_h2(float lo, float hi) {
    __half2 h = __floats2half2_rn(lo, hi);
    return *reinterpret_cast<uint32_t*>(&h);
}

#define MMA_F16(d, a, b0, b1) \
    asm volatile("mma.sync.aligned.m16n8k16.row.col.f32.f16.f16.f32 " \
        "{%0,%1,%2,%3}, {%4,%5,%6,%7}, {%8,%9}, {%0,%1,%2,%3};" \
        : "+f"((d)[0]), "+f"((d)[1]), "+f"((d)[2]), "+f"((d)[3]) \
        : "r"((a)[0]), "r"((a)[1]), "r"((a)[2]), "r"((a)[3]), "r"(b0), "r"(b1))

// ldmatrix x4: B-frags for TWO n8xk16 mma tiles in one instruction
#define LDSM_X4(r0, r1, r2, r3, addr) \
    asm volatile("ldmatrix.sync.aligned.m8n8.x4.shared.b16 {%0,%1,%2,%3}, [%4];" \
        : "=r"(r0), "=r"(r1), "=r"(r2), "=r"(r3) : "r"(addr))

#define CPA(dst, src) \
    asm volatile("cp.async.cg.shared.global [%0], [%1], 16;" :: "r"(dst), "l"(src))
#define CPA_COMMIT asm volatile("cp.async.commit_group;" ::: "memory")
#define CPA_WAIT0  asm volatile("cp.async.wait_group 0;" ::: "memory")
#define CPA_WAIT1  asm volatile("cp.async.wait_group 1;" ::: "memory")

// ============================ QKV: merged 1-wave, 3xFP16 split GEMM (R10/R13 proven) ============================
#define WS 132
#define OFF_W1  16896
#define OFF_XF  33792
#define OFF_XHI 43008
#define OFF_XLO 47360
#define SMEM_QKV (51712 * 4)
#define INV64 0.015625f

__global__ __launch_bounds__(256, 1)
void qkv5(const float* __restrict__ x,
          const float* __restrict__ Wq, const float* __restrict__ bq,
          const float* __restrict__ Wk, const float* __restrict__ bk,
          const float* __restrict__ Wv, const float* __restrict__ bv) {
    extern __shared__ float sm[];
    uint32_t sbase = smem_u32(sm);

    int n0 = blockIdx.x * 64;
    int b = blockIdx.y;
    const float* xb = x + (size_t)b * CC * NN;
    const float* Bm[3] = {bq, bk, bv};

    int tid = threadIdx.x;
    int w = tid >> 5, lane = tid & 31;
    int g = lane >> 2, t = lane & 3;
    int crow = w * 16 + g;

    // ---- prologue: W0(Wq) | X | W1(Wk) in separate groups ----
    #pragma unroll
    for (int it = 0; it < 16; it++) {
        int i = tid + it * 256;
        int r = i >> 5, c4 = (i & 31) << 2;
        CPA(sbase + (uint32_t)(r * WS + c4) * 4, Wq + (size_t)r * CC + c4);
    }
    CPA_COMMIT;
    #pragma unroll
    for (int it = 0; it < 8; it++) {
        int i = tid + it * 256;
        int r = i >> 4, n4 = (i & 15) << 2;
        CPA(sbase + (uint32_t)(OFF_XF + r * 72 + n4) * 4, xb + (size_t)r * NN + n0 + n4);
    }
    CPA_COMMIT;
    #pragma unroll
    for (int it = 0; it < 16; it++) {
        int i = tid + it * 256;
        int r = i >> 5, c4 = (i & 31) << 2;
        CPA(sbase + (uint32_t)(OFF_W1 + r * WS + c4) * 4, Wk + (size_t)r * CC + c4);
    }
    CPA_COMMIT;

    CPA_WAIT1;
    __syncthreads();

    // ---- convert X -> transposed fp16 hi/lo tiles [n][k], stride 136 halves ----
    {
        int n = tid >> 2;
        int kbase = (tid & 3) * 32;
        uint32_t* XhiT = (uint32_t*)sm + OFF_XHI;
        uint32_t* XloT = (uint32_t*)sm + OFF_XLO;
        #pragma unroll
        for (int j = 0; j < 16; j++) {
            int k = kbase + 2 * j;
            float f0 = sm[OFF_XF + k * 72 + n];
            float f1 = sm[OFF_XF + (k + 1) * 72 + n];
            __half h0 = __float2half_rn(f0), h1 = __float2half_rn(f1);
            uint32_t hi = pack_h2(__half2float(h0), __half2float(h1));
            uint32_t lo = pack_h2(f0 - __half2float(h0), f1 - __half2float(h1));
            XhiT[n * 68 + (kbase >> 1) + j] = hi;
            XloT[n * 68 + (kbase >> 1) + j] = lo;
        }
    }
    __syncthreads();

    const uint32_t* Xhi = (const uint32_t*)sm + OFF_XHI;
    const uint32_t* Xlo = (const uint32_t*)sm + OFF_XLO;

    #pragma unroll 1
    for (int m = 0; m < 3; m++) {
        const float* Wb = sm + ((m & 1) ? OFF_W1 : 0);

        // ---- hoist W fp16 hi/lo A-frags (scaled x64) ----
        uint32_t wa_hi[8][4], wa_lo[8][4];
        #pragma unroll
        for (int ko = 0; ko < 8; ko++) {
            #pragma unroll
            for (int q = 0; q < 4; q++) {
                int row = crow + ((q & 1) ? 8 : 0);
                int kk = ko * 16 + 2 * t + ((q >> 1) ? 8 : 0);
                float2 p = *(const float2*)&Wb[row * WS + kk];
                p.x *= 64.0f; p.y *= 64.0f;
                __half h0 = __float2half_rn(p.x), h1 = __float2half_rn(p.y);
                wa_hi[ko][q] = pack_h2(__half2float(h0), __half2float(h1));
                wa_lo[ko][q] = pack_h2(p.x - __half2float(h0), p.y - __half2float(h1));
            }
        }
        __syncthreads();

        if (m == 0) {
            #pragma unroll
            for (int it = 0; it < 16; it++) {
                int i = tid + it * 256;
                int r = i >> 5, c4 = (i & 31) << 2;
                CPA(sbase + (uint32_t)(r * WS + c4) * 4, Wv + (size_t)r * CC + c4);
            }
            CPA_COMMIT;
        }

        // ---- 3xFP16 GEMM ----
        float acc[8][4] = {};
        #pragma unroll
        for (int ko = 0; ko < 8; ko++) {
            #pragma unroll
            for (int nt = 0; nt < 8; nt++) {
                int i0 = (nt * 8 + g) * 68 + ko * 8 + t;
                uint32_t bh0 = Xhi[i0], bh1 = Xhi[i0 + 4];
                uint32_t bl0 = Xlo[i0], bl1 = Xlo[i0 + 4];
                MMA_F16(acc[nt], wa_lo[ko], bh0, bh1);
                MMA_F16(acc[nt], wa_hi[ko], bl0, bl1);
                MMA_F16(acc[nt], wa_hi[ko], bh0, bh1);
            }
        }
        __syncthreads();

        const float* bias = Bm[m];
        float b0v = bias[crow], b1v = bias[crow + 8];
        float qs = (m == 0) ? LOG2E : 1.0f;
        __half* st_h = (__half*)(sm + OFF_XF);

        if (m != 2) {
            // q,k: stage fp16 [n][c] stride 136
            #pragma unroll
            for (int nt = 0; nt < 8; nt++) {
                int n = nt * 8 + 2 * t;
                st_h[n * 136 + crow]           = __float2half_rn((acc[nt][0] * INV64 + b0v) * qs);
                st_h[(n + 1) * 136 + crow]     = __float2half_rn((acc[nt][1] * INV64 + b0v) * qs);
                st_h[n * 136 + crow + 8]       = __float2half_rn((acc[nt][2] * INV64 + b1v) * qs);
                st_h[(n + 1) * 136 + crow + 8] = __float2half_rn((acc[nt][3] * INV64 + b1v) * qs);
            }
            __syncthreads();
            __half* out = ((m == 0) ? g_qh : g_kh) + ((size_t)b * NN + n0) * CC;
            #pragma unroll
            for (int it = 0; it < 4; it++) {
                int i = tid + it * 256;
                int r = i >> 4, c8 = (i & 15) << 3;
                *(uint4*)(out + (size_t)r * CC + c8) = *(uint4*)&st_h[r * 136 + c8];
            }
        } else {
            // v: stage fp16 [c][n] stride 72
            #pragma unroll
            for (int nt = 0; nt < 8; nt++) {
                int n = nt * 8 + 2 * t;
                *(__half2*)&st_h[crow * 72 + n] =
                    __floats2half2_rn(acc[nt][0] * INV64 + b0v, acc[nt][1] * INV64 + b0v);
                *(__half2*)&st_h[(crow + 8) * 72 + n] =
                    __floats2half2_rn(acc[nt][2] * INV64 + b1v, acc[nt][3] * INV64 + b1v);
            }
            __syncthreads();
            __half* out = g_vh + (size_t)b * CC * NN + n0;
            #pragma unroll
            for (int it = 0; it < 4; it++) {
                int i = tid + it * 256;
                int r = i >> 3, n8 = (i & 7) << 3;
                *(uint4*)(out + (size_t)r * NN + n8) = *(uint4*)&st_h[r * 72 + n8];
            }
        }

        if (m == 0) CPA_WAIT1;
        if (m == 1) CPA_WAIT0;
        __syncthreads();
    }
}

// ============================ flash v10: R13 flash9 + fp16 partial writes ============================
#define FS 136
#define OFFK 17408
#define OFFV 52224
#define FB 17408
#define SMEM_FLASH (87040 * 2)
#define ONES2 0x3C003C00u

__global__ __launch_bounds__(256, 1)
void flash10() {
    extern __shared__ __half smh[];
    uint32_t sbase = smem_u32(smh);

    int tid = threadIdx.x;
    int w = tid >> 5, lane = tid & 31;
    int g = lane >> 2, t = lane & 3;
    int qrow = w * 16 + g;

    int lrow = (lane & 7) + ((lane >> 4) & 1) * 8;
    int lkof = ((lane >> 3) & 1) * 8;
    uint32_t laneoff = (uint32_t)(lrow * FS + lkof) * 2;

    int qtile = blockIdx.x, half = blockIdx.y, b = blockIdx.z;
    const __half* qg = g_qh + ((size_t)b * NN + (size_t)qtile * 128) * CC;
    const __half* kg = g_kh + ((size_t)b * NN + (size_t)half * 2048) * CC;
    const __half* vg = g_vh + (size_t)b * CC * NN + (size_t)half * 2048;

    #pragma unroll
    for (int it = 0; it < 8; it++) {
        int i = tid + it * 256;
        int r = i >> 4, c16 = i & 15;
        CPA(sbase + (uint32_t)(r * FS * 2 + c16 * 16), qg + (size_t)r * CC + c16 * 8);
    }
    #pragma unroll
    for (int it = 0; it < 8; it++) {
        int i = tid + it * 256;
        int r = i >> 4, c16 = i & 15;
        CPA(sbase + (uint32_t)(OFFK * 2 + r * FS * 2 + c16 * 16), kg + (size_t)r * CC + c16 * 8);
    }
    #pragma unroll
    for (int it = 0; it < 8; it++) {
        int i = tid + it * 256;
        int c = i >> 4, k16 = i & 15;
        CPA(sbase + (uint32_t)(OFFV * 2 + c * FS * 2 + k16 * 16), vg + (size_t)c * NN + k16 * 8);
    }
    CPA_COMMIT;
    CPA_WAIT0;
    __syncthreads();

    uint32_t qa[8][4];
    #pragma unroll
    for (int ko = 0; ko < 8; ko++) {
        const __half* qp = smh + qrow * FS + ko * 16;
        qa[ko][0] = *(const uint32_t*)(qp + 2 * t);
        qa[ko][1] = *(const uint32_t*)(qp + 8 * FS + 2 * t);
        qa[ko][2] = *(const uint32_t*)(qp + 2 * t + 8);
        qa[ko][3] = *(const uint32_t*)(qp + 8 * FS + 2 * t + 8);
    }
    __syncthreads();

    float o[16][4] = {};
    float rsacc[4] = {};

    for (int kb = 0; kb < 16; kb++) {
        int buf = kb & 1;
        if (kb < 15) {
            int m0 = (kb + 1) * 128;
            int nb = buf ^ 1;
            #pragma unroll
            for (int it = 0; it < 8; it++) {
                int i = tid + it * 256;
                int r = i >> 4, c16 = i & 15;
                CPA(sbase + (uint32_t)((OFFK + nb * FB) * 2 + r * FS * 2 + c16 * 16),
                    kg + (size_t)(m0 + r) * CC + c16 * 8);
            }
            #pragma unroll
            for (int it = 0; it < 8; it++) {
                int i = tid + it * 256;
                int c = i >> 4, k16 = i & 15;
                CPA(sbase + (uint32_t)((OFFV + nb * FB) * 2 + c * FS * 2 + k16 * 16),
                    vg + (size_t)c * NN + m0 + k16 * 8);
            }
            CPA_COMMIT;
        }

        uint32_t kaddr = sbase + (uint32_t)(OFFK + buf * FB) * 2 + laneoff;
        uint32_t vaddr = sbase + (uint32_t)(OFFV + buf * FB) * 2 + laneoff;

        uint32_t pa[8][4];
        #pragma unroll
        for (int nh = 0; nh < 2; nh++) {
            float sacc[8][4] = {};
            #pragma unroll
            for (int ko = 0; ko < 8; ko++) {
                #pragma unroll
                for (int np = 0; np < 4; np++) {
                    uint32_t a = kaddr + (uint32_t)(((nh * 4 + np) * 16) * FS + ko * 16) * 2;
                    uint32_t r0, r1, r2, r3;
                    LDSM_X4(r0, r1, r2, r3, a);
                    MMA_F16(sacc[np * 2 + 0], qa[ko], r0, r1);
                    MMA_F16(sacc[np * 2 + 1], qa[ko], r2, r3);
                }
            }
            #pragma unroll
            for (int nt = 0; nt < 8; nt++) {
                pa[nh * 4 + (nt >> 1)][(nt & 1) * 2 + 0] =
                    ex2_h2(pack_h2(sacc[nt][0], sacc[nt][1]));
                pa[nh * 4 + (nt >> 1)][(nt & 1) * 2 + 1] =
                    ex2_h2(pack_h2(sacc[nt][2], sacc[nt][3]));
            }
        }

        #pragma unroll
        for (int kf = 0; kf < 8; kf++)
            MMA_F16(rsacc, pa[kf], ONES2, ONES2);

        #pragma unroll
        for (int kf = 0; kf < 8; kf++) {
            #pragma unroll
            for (int cp = 0; cp < 8; cp++) {
                uint32_t a = vaddr + (uint32_t)((cp * 16) * FS + kf * 16) * 2;
                uint32_t r0, r1, r2, r3;
                LDSM_X4(r0, r1, r2, r3, a);
                MMA_F16(o[cp * 2 + 0], pa[kf], r0, r1);
                MMA_F16(o[cp * 2 + 1], pa[kf], r2, r3);
            }
        }

        CPA_WAIT0;
        __syncthreads();
    }

    if (t == 0) {
        float* gl = g_lsum + (size_t)half * BB * NN + (size_t)b * NN + qtile * 128;
        gl[qrow] = rsacc[0];
        gl[qrow + 8] = rsacc[2];
    }

    // ---- stage O (f32, stride 132) then write fp16 partials ----
    float* smf = (float*)smh;
    #pragma unroll
    for (int cn = 0; cn < 16; cn++) {
        int c0 = cn * 8 + 2 * t;
        smf[c0 * 132 + qrow]           = o[cn][0];
        smf[(c0 + 1) * 132 + qrow]     = o[cn][1];
        smf[c0 * 132 + qrow + 8]       = o[cn][2];
        smf[(c0 + 1) * 132 + qrow + 8] = o[cn][3];
    }
    __syncthreads();
    __half* gp = g_ph + (size_t)half * BB * CC * NN + (size_t)b * CC * NN + (size_t)qtile * 128;
    #pragma unroll
    for (int it = 0; it < 8; it++) {
        int i = tid + it * 256;
        int c = i >> 4, q8 = (i & 15) << 3;
        float4 a = *(float4*)&smf[c * 132 + q8];
        float4 d = *(float4*)&smf[c * 132 + q8 + 4];
        uint4 packed;
        packed.x = pack_h2(a.x, a.y);
        packed.y = pack_h2(a.z, a.w);
        packed.z = pack_h2(d.x, d.y);
        packed.w = pack_h2(d.z, d.w);
        *(uint4*)(gp + (size_t)c * NN + q8) = packed;
    }
}

// ============================ combine halves (fp16 partials) ============================
__global__ __launch_bounds__(256)
void combine_kernel(float* __restrict__ out) {
    int idx = blockIdx.x * 256 + threadIdx.x;
    size_t e = (size_t)idx * 8;
    int n = (int)(e & (NN - 1));
    int b = (int)(e >> 19);                 // CC*NN = 2^19
    uint4 u0 = *(const uint4*)(g_ph + e);
    uint4 u1 = *(const uint4*)(g_ph + (size_t)BB * CC * NN + e);
    float4 l0a = *(const float4*)(g_lsum + (size_t)b * NN + n);
    float4 l0b = *(const float4*)(g_lsum + (size_t)b * NN + n + 4);
    float4 l1a = *(const float4*)(g_lsum + (size_t)BB * NN + (size_t)b * NN + n);
    float4 l1b = *(const float4*)(g_lsum + (size_t)BB * NN + (size_t)b * NN + n + 4);

    float2 p00 = __half22float2(*(__half2*)&u0.x);
    float2 p01 = __half22float2(*(__half2*)&u0.y);
    float2 p02 = __half22float2(*(__half2*)&u0.z);
    float2 p03 = __half22float2(*(__half2*)&u0.w);
    float2 p10 = __half22float2(*(__half2*)&u1.x);
    float2 p11 = __half22float2(*(__half2*)&u1.y);
    float2 p12 = __half22float2(*(__half2*)&u1.z);
    float2 p13 = __half22float2(*(__half2*)&u1.w);

    float4 r0, r1;
    r0.x = (p00.x + p10.x) / (l0a.x + l1a.x);
    r0.y = (p00.y + p10.y) / (l0a.y + l1a.y);
    r0.z = (p01.x + p11.x) / (l0a.z + l1a.z);
    r0.w = (p01.y + p11.y) / (l0a.w + l1a.w);
    r1.x = (p02.x + p12.x) / (l0b.x + l1b.x);
    r1.y = (p02.y + p12.y) / (l0b.y + l1b.y);
    r1.z = (p03.x + p13.x) / (l0b.z + l1b.z);
    r1.w = (p03.y + p13.y) / (l0b.w + l1b.w);
    *(float4*)(out + e) = r0;
    *(float4*)(out + e + 4) = r1;
}

// ============================ launch ============================
extern "C" void kernel_launch(void* const* d_in, const int* in_sizes, int n_in,
                              void* d_out, int out_size) {
    const float* x  = (const float*)d_in[0];
    const float* Wq = (const float*)d_in[1];
    const float* bq = (const float*)d_in[2];
    const float* Wk = (const float*)d_in[3];
    const float* bk = (const float*)d_in[4];
    const float* Wv = (const float*)d_in[5];
    const float* bv = (const float*)d_in[6];
    float* out = (float*)d_out;

    cudaFuncSetAttribute(qkv5, cudaFuncAttributeMaxDynamicSharedMemorySize, SMEM_QKV);
    dim3 gq(NN / 64, BB);
    qkv5<<<gq, 256, SMEM_QKV>>>(x, Wq, bq, Wk, bk, Wv, bv);

    cudaFuncSetAttribute(flash10, cudaFuncAttributeMaxDynamicSharedMemorySize, SMEM_FLASH);
    dim3 gf(NN / 128, 2, BB);
    flash10<<<gf, 256, SMEM_FLASH>>>();

    combine_kernel<<<(BB * CC * NN / 8) / 256, 256>>>(out);
}